// round 2
// baseline (speedup 1.0000x reference)
#include <cuda_runtime.h>
#include <cstdint>

// Problem constants (fixed by the dataset)
constexpr int Bc  = 2;
constexpr int Sc  = 2048;
constexpr int Dc  = 1024;
constexpr int Hc  = 16;
constexpr int DKc = 64;
constexpr int DFFc = 4096;
constexpr int Mr  = Bc * Sc;          // 4096 rows
constexpr float EPSc = 1e-5f;

// ---------------------------------------------------------------------------
// Scratch (static __device__ arrays; no allocation at runtime)
// ---------------------------------------------------------------------------
__device__ float g_Q  [(size_t)Bc * Hc * Sc * DKc];   // 16 MB, [B,H,S,DK]
__device__ float g_ctx[(size_t)Mr * Dc];              // 16 MB, concat [M,D]
__device__ float g_y  [(size_t)Mr * Dc];              // 16 MB, pre-LN buffer
__device__ float g_x1 [(size_t)Mr * Dc];              // 16 MB
__device__ float g_h  [(size_t)Mr * DFFc];            // 64 MB, FFN hidden

// ---------------------------------------------------------------------------
// SGEMM: C[M,N] = A[M,K] @ B[K,N] + bias (+ optional residual / relu)
// 128x128 tile, BK=16, 256 threads, 8x8 register micro-tile.
// Global->register prefetch of the next K-tile overlaps GMEM latency with FMAs.
// OUTMODE 0: row-major [M,N]. OUTMODE 1: split-head [B,H,S,DK] (N = H*DK).
// ---------------------------------------------------------------------------
template<bool RELU, bool RESID, int OUTMODE>
__global__ __launch_bounds__(256)
void gemm128(const float* __restrict__ A, const float* __restrict__ B,
             const float* __restrict__ bias, const float* __restrict__ R,
             float* __restrict__ C, int N, int K)
{
    __shared__ float As[16][128];   // transposed: As[k][m]
    __shared__ float Bs[16][132];   // padded to dodge store conflicts

    const int t     = threadIdx.x;
    const int mBase = blockIdx.y * 128;
    const int nBase = blockIdx.x * 128;
    const int tx    = t & 15;
    const int ty    = t >> 4;
    const int row0  = ty * 8;
    const int col0  = tx * 8;

    // Per-thread load coordinates (2 float4 each for A and B)
    const int ar0 = t >> 1;                 // 0..127   (A row,     i=0)
    const int ac0 = (t & 1) * 4;            // 0 or 4   (A col base, i=0)
    const int ar1 = ar0;                    // second half of same row
    const int ac1 = ac0 + 8;                // 8 or 12
    const int br0 = t >> 5;                 // 0..7     (B row, i=0)
    const int bc0 = (t & 31) * 4;           // 0..124
    const int br1 = br0 + 8;                // 8..15    (B row, i=1)

    const float* Aptr = A + (size_t)(mBase + ar0) * K;
    const float* Bptr = B + nBase;

    float acc[8][8];
    #pragma unroll
    for (int i = 0; i < 8; i++)
        #pragma unroll
        for (int j = 0; j < 8; j++) acc[i][j] = 0.f;

    // Preload first tile
    float4 aReg0 = *reinterpret_cast<const float4*>(Aptr + ac0);
    float4 aReg1 = *reinterpret_cast<const float4*>(Aptr + ac1);
    float4 bReg0 = *reinterpret_cast<const float4*>(Bptr + (size_t)br0 * N + bc0);
    float4 bReg1 = *reinterpret_cast<const float4*>(Bptr + (size_t)br1 * N + bc0);

    for (int k0 = 0; k0 < K; k0 += 16) {
        // Stage current tile to shared
        As[ac0 + 0][ar0] = aReg0.x;  As[ac0 + 1][ar0] = aReg0.y;
        As[ac0 + 2][ar0] = aReg0.z;  As[ac0 + 3][ar0] = aReg0.w;
        As[ac1 + 0][ar1] = aReg1.x;  As[ac1 + 1][ar1] = aReg1.y;
        As[ac1 + 2][ar1] = aReg1.z;  As[ac1 + 3][ar1] = aReg1.w;
        *reinterpret_cast<float4*>(&Bs[br0][bc0]) = bReg0;
        *reinterpret_cast<float4*>(&Bs[br1][bc0]) = bReg1;
        __syncthreads();

        // Prefetch next tile into registers (overlaps with FMAs below)
        if (k0 + 16 < K) {
            const float* An = Aptr + k0 + 16;
            const float* Bn = Bptr + (size_t)(k0 + 16) * N;
            aReg0 = *reinterpret_cast<const float4*>(An + ac0);
            aReg1 = *reinterpret_cast<const float4*>(An + ac1);
            bReg0 = *reinterpret_cast<const float4*>(Bn + (size_t)br0 * N + bc0);
            bReg1 = *reinterpret_cast<const float4*>(Bn + (size_t)br1 * N + bc0);
        }

        #pragma unroll
        for (int kk = 0; kk < 16; kk++) {
            float a[8], b[8];
            #pragma unroll
            for (int i = 0; i < 8; i++) a[i] = As[kk][row0 + i];
            #pragma unroll
            for (int j = 0; j < 8; j++) b[j] = Bs[kk][col0 + j];
            #pragma unroll
            for (int i = 0; i < 8; i++)
                #pragma unroll
                for (int j = 0; j < 8; j++)
                    acc[i][j] = fmaf(a[i], b[j], acc[i][j]);
        }
        __syncthreads();
    }

    // Epilogue
    #pragma unroll
    for (int i = 0; i < 8; i++) {
        int m = mBase + row0 + i;
        #pragma unroll
        for (int j = 0; j < 8; j++) {
            int n = nBase + col0 + j;
            float v = acc[i][j] + bias[n];
            if (RELU)  v = fmaxf(v, 0.f);
            if (RESID) v += R[(size_t)m * N + n];
            if (OUTMODE == 0) {
                C[(size_t)m * N + n] = v;
            } else {
                int b_ = m >> 11;        // m / S  (S = 2048)
                int s_ = m & 2047;
                int h_ = n >> 6;         // n / DK (DK = 64)
                int dk = n & 63;
                C[((((size_t)b_ * Hc + h_) * Sc + s_) << 6) + dk] = v;
            }
        }
    }
}

// ---------------------------------------------------------------------------
// Flash attention (causal), Br = Bc = 64, DK = 64.
// grid: (S/64, B*H), 256 threads. Thread t: row = t>>2, quad = t&3.
// Each thread owns 16 output dims (quad*16..+15) and 16 score cols per tile.
// ---------------------------------------------------------------------------
__global__ __launch_bounds__(256)
void attn_kernel(const float* __restrict__ Q, const float* __restrict__ K,
                 const float* __restrict__ V, float* __restrict__ ctx)
{
    extern __shared__ float sm[];
    float (*Qs)[65] = (float(*)[65])(sm);
    float (*Ks)[65] = (float(*)[65])(sm + 64 * 65);
    float (*Vs)[65] = (float(*)[65])(sm + 2 * 64 * 65);
    float (*Ps)[65] = (float(*)[65])(sm + 3 * 64 * 65);

    const int t   = threadIdx.x;
    const int q0  = blockIdx.x * 64;
    const int bh  = blockIdx.y;
    const float* Qb = Q + ((size_t)bh * Sc + q0) * 64;
    const float* Kb = K + (size_t)bh * Sc * 64;
    const float* Vb = V + (size_t)bh * Sc * 64;

    // Load Q tile (64x64) vectorized
    for (int i = t; i < 64 * 16; i += 256) {
        int r  = i >> 4;
        int c4 = (i & 15) * 4;
        float4 v = *reinterpret_cast<const float4*>(&Qb[r * 64 + c4]);
        Qs[r][c4 + 0] = v.x; Qs[r][c4 + 1] = v.y;
        Qs[r][c4 + 2] = v.z; Qs[r][c4 + 3] = v.w;
    }

    const int row  = t >> 2;
    const int quad = t & 3;
    const int d0   = quad * 16;

    float acc[16];
    #pragma unroll
    for (int i = 0; i < 16; i++) acc[i] = 0.f;
    float mrow = -1e30f, lrow = 0.f;

    for (int k0 = 0; k0 <= q0; k0 += 64) {
        __syncthreads();   // protect Ks/Vs/Ps from previous iteration
        for (int i = t; i < 64 * 16; i += 256) {
            int r  = i >> 4;
            int c4 = (i & 15) * 4;
            float4 kv = *reinterpret_cast<const float4*>(&Kb[(k0 + r) * 64 + c4]);
            Ks[r][c4 + 0] = kv.x; Ks[r][c4 + 1] = kv.y;
            Ks[r][c4 + 2] = kv.z; Ks[r][c4 + 3] = kv.w;
            float4 vv = *reinterpret_cast<const float4*>(&Vb[(k0 + r) * 64 + c4]);
            Vs[r][c4 + 0] = vv.x; Vs[r][c4 + 1] = vv.y;
            Vs[r][c4 + 2] = vv.z; Vs[r][c4 + 3] = vv.w;
        }
        __syncthreads();

        // Scores: s[j] = sum_d Qs[row][d] * Ks[quad*16+j][d]
        float s[16];
        #pragma unroll
        for (int j = 0; j < 16; j++) s[j] = 0.f;
        #pragma unroll
        for (int d = 0; d < 64; d++) {
            float qd = Qs[row][d];
            #pragma unroll
            for (int j = 0; j < 16; j++)
                s[j] = fmaf(qd, Ks[d0 + j][d], s[j]);
        }
        #pragma unroll
        for (int j = 0; j < 16; j++) {
            int c = d0 + j;
            s[j] = (k0 + c <= q0 + row) ? s[j] * 0.125f : -1e9f;
        }

        // Row max (across the 4 quads of this row: lanes differ in bits 0-1)
        float mloc = s[0];
        #pragma unroll
        for (int j = 1; j < 16; j++) mloc = fmaxf(mloc, s[j]);
        mloc = fmaxf(mloc, __shfl_xor_sync(0xffffffffu, mloc, 1));
        mloc = fmaxf(mloc, __shfl_xor_sync(0xffffffffu, mloc, 2));
        float mnew  = fmaxf(mrow, mloc);
        float alpha = expf(mrow - mnew);

        float psum = 0.f;
        #pragma unroll
        for (int j = 0; j < 16; j++) {
            float p = expf(s[j] - mnew);
            Ps[row][d0 + j] = p;
            psum += p;
        }
        psum += __shfl_xor_sync(0xffffffffu, psum, 1);
        psum += __shfl_xor_sync(0xffffffffu, psum, 2);
        lrow = lrow * alpha + psum;
        mrow = mnew;
        #pragma unroll
        for (int j = 0; j < 16; j++) acc[j] *= alpha;

        __syncthreads();   // Ps complete before PV

        #pragma unroll 8
        for (int c = 0; c < 64; c++) {
            float p = Ps[row][c];
            #pragma unroll
            for (int j = 0; j < 16; j++)
                acc[j] = fmaf(p, Vs[c][d0 + j], acc[j]);
        }
    }

    // Write ctx in concat layout [B, S, H*DK]
    float inv = 1.f / lrow;
    int b_ = bh >> 4;
    int h_ = bh & 15;
    float* out = ctx + ((size_t)(b_ * Sc + q0 + row)) * Dc + h_ * 64 + d0;
    #pragma unroll
    for (int j = 0; j < 16; j++) out[j] = acc[j] * inv;
}

// ---------------------------------------------------------------------------
// LayerNorm over last dim (D = 1024). One block per row, 256 threads x float4.
// ---------------------------------------------------------------------------
__global__ __launch_bounds__(256)
void ln_kernel(const float* __restrict__ X, const float* __restrict__ gma,
               const float* __restrict__ bta, float* __restrict__ Y)
{
    const int r = blockIdx.x;
    const int t = threadIdx.x;
    float4 v = reinterpret_cast<const float4*>(X + (size_t)r * Dc)[t];
    float s = v.x + v.y + v.z + v.w;
    float q = v.x * v.x + v.y * v.y + v.z * v.z + v.w * v.w;
    #pragma unroll
    for (int o = 16; o; o >>= 1) {
        s += __shfl_xor_sync(0xffffffffu, s, o);
        q += __shfl_xor_sync(0xffffffffu, q, o);
    }
    __shared__ float ss[8], qs[8];
    __shared__ float mu_s, inv_s;
    if ((t & 31) == 0) { ss[t >> 5] = s; qs[t >> 5] = q; }
    __syncthreads();
    if (t == 0) {
        float S = 0.f, Qq = 0.f;
        #pragma unroll
        for (int i = 0; i < 8; i++) { S += ss[i]; Qq += qs[i]; }
        float mu  = S * (1.f / Dc);
        float var = Qq * (1.f / Dc) - mu * mu;
        mu_s  = mu;
        inv_s = rsqrtf(var + EPSc);
    }
    __syncthreads();
    float mu = mu_s, inv = inv_s;
    float4 gv = reinterpret_cast<const float4*>(gma)[t];
    float4 bv = reinterpret_cast<const float4*>(bta)[t];
    float4 o;
    o.x = (v.x - mu) * inv * gv.x + bv.x;
    o.y = (v.y - mu) * inv * gv.y + bv.y;
    o.z = (v.z - mu) * inv * gv.z + bv.z;
    o.w = (v.w - mu) * inv * gv.w + bv.w;
    reinterpret_cast<float4*>(Y + (size_t)r * Dc)[t] = o;
}

// ---------------------------------------------------------------------------
// Launch
// ---------------------------------------------------------------------------
extern "C" void kernel_launch(void* const* d_in, const int* in_sizes, int n_in,
                              void* d_out, int out_size)
{
    const float* query = (const float*)d_in[0];
    const float* key   = (const float*)d_in[1];
    const float* value = (const float*)d_in[2];
    // d_in[3] batch_size, d_in[4] sequence_length, d_in[5] mask (== tril): unused
    const float* Wq = (const float*)d_in[6];
    const float* bq = (const float*)d_in[7];
    const float* Wk = (const float*)d_in[8];
    const float* bk = (const float*)d_in[9];
    const float* Wv = (const float*)d_in[10];
    const float* bv = (const float*)d_in[11];
    const float* Wo = (const float*)d_in[12];
    const float* bo = (const float*)d_in[13];
    const float* ln1_g = (const float*)d_in[14];
    const float* ln1_b = (const float*)d_in[15];
    const float* W1 = (const float*)d_in[16];
    const float* b1 = (const float*)d_in[17];
    const float* W2 = (const float*)d_in[18];
    const float* b2 = (const float*)d_in[19];
    const float* ln2_g = (const float*)d_in[20];
    const float* ln2_b = (const float*)d_in[21];

    float* out   = (float*)d_out;
    float* x2Out = out;
    float* kOut  = out + (size_t)Bc * Hc * Sc * DKc;      // + 4194304
    float* vOut  = kOut + (size_t)Bc * Hc * Sc * DKc;     // + 8388608

    float *pQ, *pCtx, *pY, *pX1, *pH;
    cudaGetSymbolAddress((void**)&pQ,   g_Q);
    cudaGetSymbolAddress((void**)&pCtx, g_ctx);
    cudaGetSymbolAddress((void**)&pY,   g_y);
    cudaGetSymbolAddress((void**)&pX1,  g_x1);
    cudaGetSymbolAddress((void**)&pH,   g_h);

    dim3 blk(256);
    dim3 gridD(Dc / 128, Mr / 128);     // (8, 32)
    dim3 gridF(DFFc / 128, Mr / 128);   // (32, 32)

    // 1. QKV projections (K, V straight into d_out in [B,H,S,DK] layout)
    gemm128<false, false, 1><<<gridD, blk>>>(query, Wq, bq, nullptr, pQ,   Dc, Dc);
    gemm128<false, false, 1><<<gridD, blk>>>(key,   Wk, bk, nullptr, kOut, Dc, Dc);
    gemm128<false, false, 1><<<gridD, blk>>>(value, Wv, bv, nullptr, vOut, Dc, Dc);

    // 2. Causal flash attention -> ctx (concat layout)
    const size_t attn_smem = 4 * 64 * 65 * sizeof(float);   // 66560 B
    cudaFuncSetAttribute(attn_kernel,
                         cudaFuncAttributeMaxDynamicSharedMemorySize,
                         (int)attn_smem);
    dim3 agrid(Sc / 64, Bc * Hc);       // (32, 32)
    attn_kernel<<<agrid, blk, attn_smem>>>(pQ, kOut, vOut, pCtx);

    // 3. Output projection + residual(query) -> y; LN1 -> x1
    gemm128<false, true, 0><<<gridD, blk>>>(pCtx, Wo, bo, query, pY, Dc, Dc);
    ln_kernel<<<Mr, blk>>>(pY, ln1_g, ln1_b, pX1);

    // 4. FFN: relu(x1 @ W1 + b1) -> h ; h @ W2 + b2 + x1 -> y ; LN2 -> x2
    gemm128<true,  false, 0><<<gridF, blk>>>(pX1, W1, b1, nullptr, pH, DFFc, Dc);
    gemm128<false, true,  0><<<gridD, blk>>>(pH,  W2, b2, pX1,     pY, Dc, DFFc);
    ln_kernel<<<Mr, blk>>>(pY, ln2_g, ln2_b, x2Out);
}

// round 3
// speedup vs baseline: 1.3059x; 1.3059x over previous
#include <cuda_runtime.h>
#include <cuda_bf16.h>
#include <cstdint>

// Problem constants (fixed by the dataset)
constexpr int Bc  = 2;
constexpr int Sc  = 2048;
constexpr int Dc  = 1024;
constexpr int Hc  = 16;
constexpr int DKc = 64;
constexpr int DFFc = 4096;
constexpr int Mr  = Bc * Sc;          // 4096 rows
constexpr float EPSc = 1e-5f;

// ---------------------------------------------------------------------------
// Scratch (static __device__ arrays; no allocation at runtime)
// ---------------------------------------------------------------------------
__device__ float g_Q  [(size_t)Bc * Hc * Sc * DKc];   // 16 MB, [B,H,S,DK]
__device__ float g_ctx[(size_t)Mr * Dc];              // 16 MB, concat [M,D]
__device__ float g_y  [(size_t)Mr * Dc];              // 16 MB, pre-LN buffer
__device__ float g_x1 [(size_t)Mr * Dc];              // 16 MB
__device__ float g_h  [(size_t)Mr * DFFc];            // 64 MB, FFN hidden

static __device__ __forceinline__ uint32_t cvta_s(const void* p) {
    return (uint32_t)__cvta_generic_to_shared(p);
}

#define LDSM4(r, addr)                                                        \
    asm volatile("ldmatrix.sync.aligned.m8n8.x4.shared.b16 {%0,%1,%2,%3},[%4];" \
                 : "=r"((r)[0]), "=r"((r)[1]), "=r"((r)[2]), "=r"((r)[3])     \
                 : "r"(addr))

#define LDSM4T(r0, r1, r2, r3, addr)                                          \
    asm volatile("ldmatrix.sync.aligned.m8n8.x4.trans.shared.b16 {%0,%1,%2,%3},[%4];" \
                 : "=r"(r0), "=r"(r1), "=r"(r2), "=r"(r3)                     \
                 : "r"(addr))

#define MMA_BF16(c, a, b)                                                     \
    asm volatile("mma.sync.aligned.m16n8k16.row.col.f32.bf16.bf16.f32 "       \
                 "{%0,%1,%2,%3},{%4,%5,%6,%7},{%8,%9},{%0,%1,%2,%3};"         \
                 : "+f"((c)[0]), "+f"((c)[1]), "+f"((c)[2]), "+f"((c)[3])     \
                 : "r"((a)[0]), "r"((a)[1]), "r"((a)[2]), "r"((a)[3]),        \
                   "r"((b)[0]), "r"((b)[1]))

// ---------------------------------------------------------------------------
// Tensor-core GEMM with bf16 split-3 (fp32-accurate):
//   x = hi + lo (bf16 each); C += Ahi*Bhi + Ahi*Blo + Alo*Bhi
// C[M,N] = A[M,K] @ B[K,N] + bias (+ optional residual / relu)
// Block tile 128x128, BK=32, 256 threads (8 warps, 2x4, 64x32 warp tiles).
// OUTMODE 0: row-major [M,N]. OUTMODE 1: split-head [B,H,S,DK] (N = H*DK).
// ---------------------------------------------------------------------------
template<bool RELU, bool RESID, int OUTMODE>
__global__ __launch_bounds__(256, 1)
void gemm_mma(const float* __restrict__ A, const float* __restrict__ B,
              const float* __restrict__ bias, const float* __restrict__ R,
              float* __restrict__ C, int N, int K)
{
    constexpr int AP = 40;    // A smem pitch (elems): 80B -> 5x16B, rot mod 8
    constexpr int BP = 136;   // B smem pitch (elems): 272B -> 17x16B, rot mod 8
    __shared__ __nv_bfloat16 Ah[128][AP], Al[128][AP];
    __shared__ __nv_bfloat16 Bh[32][BP],  Bl[32][BP];

    const int t     = threadIdx.x;
    const int mBase = blockIdx.y * 128;
    const int nBase = blockIdx.x * 128;
    const int warp  = t >> 5;
    const int lane  = t & 31;
    const int wm    = (warp >> 2) * 64;   // warp row offset in tile
    const int wn    = (warp & 3) * 32;    // warp col offset in tile

    // Producer coordinates
    const int arow = t >> 3;          // 0..31 (+32*i)
    const int acol = (t & 7) * 4;     // 0..28
    const int brow = t >> 5;          // 0..7  (+8*i)
    const int bcol = (t & 31) * 4;    // 0..124

    float c[4][4][4] = {};

    float4 aR[4], bR[4];
    #pragma unroll
    for (int i = 0; i < 4; i++) {
        aR[i] = *reinterpret_cast<const float4*>(
            &A[(size_t)(mBase + arow + 32 * i) * K + acol]);
        bR[i] = *reinterpret_cast<const float4*>(
            &B[(size_t)(brow + 8 * i) * N + nBase + bcol]);
    }

    for (int k0 = 0; k0 < K; k0 += 32) {
        // Stage current fp32 tile as bf16 hi/lo
        #pragma unroll
        for (int i = 0; i < 4; i++) {
            float av[4] = {aR[i].x, aR[i].y, aR[i].z, aR[i].w};
            #pragma unroll
            for (int j = 0; j < 4; j++) {
                float x = av[j];
                __nv_bfloat16 h = __float2bfloat16(x);
                __nv_bfloat16 l = __float2bfloat16(x - __bfloat162float(h));
                Ah[arow + 32 * i][acol + j] = h;
                Al[arow + 32 * i][acol + j] = l;
            }
            float bv[4] = {bR[i].x, bR[i].y, bR[i].z, bR[i].w};
            #pragma unroll
            for (int j = 0; j < 4; j++) {
                float x = bv[j];
                __nv_bfloat16 h = __float2bfloat16(x);
                __nv_bfloat16 l = __float2bfloat16(x - __bfloat162float(h));
                Bh[brow + 8 * i][bcol + j] = h;
                Bl[brow + 8 * i][bcol + j] = l;
            }
        }
        __syncthreads();

        // Prefetch next K-tile (overlaps with MMAs)
        if (k0 + 32 < K) {
            #pragma unroll
            for (int i = 0; i < 4; i++) {
                aR[i] = *reinterpret_cast<const float4*>(
                    &A[(size_t)(mBase + arow + 32 * i) * K + k0 + 32 + acol]);
                bR[i] = *reinterpret_cast<const float4*>(
                    &B[(size_t)(k0 + 32 + brow + 8 * i) * N + nBase + bcol]);
            }
        }

        #pragma unroll
        for (int ks = 0; ks < 32; ks += 16) {
            uint32_t ah[4][4], al_[4][4], bhf[4][2], blf[4][2];
            #pragma unroll
            for (int mt = 0; mt < 4; mt++) {
                uint32_t ad = cvta_s(&Ah[wm + mt * 16 + (lane & 15)]
                                       [ks + (lane >> 4) * 8]);
                LDSM4(ah[mt], ad);
                ad = cvta_s(&Al[wm + mt * 16 + (lane & 15)]
                              [ks + (lane >> 4) * 8]);
                LDSM4(al_[mt], ad);
            }
            #pragma unroll
            for (int p = 0; p < 2; p++) {
                uint32_t ad = cvta_s(&Bh[ks + (lane & 15)]
                                       [wn + p * 16 + (lane >> 4) * 8]);
                LDSM4T(bhf[2 * p][0], bhf[2 * p][1],
                       bhf[2 * p + 1][0], bhf[2 * p + 1][1], ad);
                ad = cvta_s(&Bl[ks + (lane & 15)]
                              [wn + p * 16 + (lane >> 4) * 8]);
                LDSM4T(blf[2 * p][0], blf[2 * p][1],
                       blf[2 * p + 1][0], blf[2 * p + 1][1], ad);
            }
            #pragma unroll
            for (int mt = 0; mt < 4; mt++)
                #pragma unroll
                for (int nt = 0; nt < 4; nt++) {
                    MMA_BF16(c[mt][nt], ah[mt],  bhf[nt]);
                    MMA_BF16(c[mt][nt], ah[mt],  blf[nt]);
                    MMA_BF16(c[mt][nt], al_[mt], bhf[nt]);
                }
        }
        __syncthreads();
    }

    // Epilogue: fragment (mt,nt): rows wm+mt*16 + lane/4 (+8), cols wn+nt*8 + (lane&3)*2
    #pragma unroll
    for (int mt = 0; mt < 4; mt++) {
        #pragma unroll
        for (int nt = 0; nt < 4; nt++) {
            int r0  = mBase + wm + mt * 16 + (lane >> 2);
            int col = nBase + wn + nt * 8 + (lane & 3) * 2;
            float b0 = bias[col], b1 = bias[col + 1];
            #pragma unroll
            for (int h2 = 0; h2 < 2; h2++) {
                int m = r0 + h2 * 8;
                float v0 = c[mt][nt][h2 * 2 + 0] + b0;
                float v1 = c[mt][nt][h2 * 2 + 1] + b1;
                if (RELU)  { v0 = fmaxf(v0, 0.f); v1 = fmaxf(v1, 0.f); }
                if (RESID) {
                    v0 += R[(size_t)m * N + col];
                    v1 += R[(size_t)m * N + col + 1];
                }
                if (OUTMODE == 0) {
                    *reinterpret_cast<float2*>(&C[(size_t)m * N + col]) =
                        make_float2(v0, v1);
                } else {
                    int b_ = m >> 11;         // m / S
                    int s_ = m & 2047;
                    int h_ = col >> 6;        // n / DK
                    int dk = col & 63;
                    size_t o = ((((size_t)b_ * Hc + h_) * Sc + s_) << 6) + dk;
                    *reinterpret_cast<float2*>(&C[o]) = make_float2(v0, v1);
                }
            }
        }
    }
}

// ---------------------------------------------------------------------------
// Flash attention (causal), Br = Bc = 64, DK = 64.  (unchanged from R2)
// ---------------------------------------------------------------------------
__global__ __launch_bounds__(256)
void attn_kernel(const float* __restrict__ Q, const float* __restrict__ K,
                 const float* __restrict__ V, float* __restrict__ ctx)
{
    extern __shared__ float sm[];
    float (*Qs)[65] = (float(*)[65])(sm);
    float (*Ks)[65] = (float(*)[65])(sm + 64 * 65);
    float (*Vs)[65] = (float(*)[65])(sm + 2 * 64 * 65);
    float (*Ps)[65] = (float(*)[65])(sm + 3 * 64 * 65);

    const int t   = threadIdx.x;
    const int q0  = blockIdx.x * 64;
    const int bh  = blockIdx.y;
    const float* Qb = Q + ((size_t)bh * Sc + q0) * 64;
    const float* Kb = K + (size_t)bh * Sc * 64;
    const float* Vb = V + (size_t)bh * Sc * 64;

    for (int i = t; i < 64 * 16; i += 256) {
        int r  = i >> 4;
        int c4 = (i & 15) * 4;
        float4 v = *reinterpret_cast<const float4*>(&Qb[r * 64 + c4]);
        Qs[r][c4 + 0] = v.x; Qs[r][c4 + 1] = v.y;
        Qs[r][c4 + 2] = v.z; Qs[r][c4 + 3] = v.w;
    }

    const int row  = t >> 2;
    const int quad = t & 3;
    const int d0   = quad * 16;

    float acc[16];
    #pragma unroll
    for (int i = 0; i < 16; i++) acc[i] = 0.f;
    float mrow = -1e30f, lrow = 0.f;

    for (int k0 = 0; k0 <= q0; k0 += 64) {
        __syncthreads();
        for (int i = t; i < 64 * 16; i += 256) {
            int r  = i >> 4;
            int c4 = (i & 15) * 4;
            float4 kv = *reinterpret_cast<const float4*>(&Kb[(k0 + r) * 64 + c4]);
            Ks[r][c4 + 0] = kv.x; Ks[r][c4 + 1] = kv.y;
            Ks[r][c4 + 2] = kv.z; Ks[r][c4 + 3] = kv.w;
            float4 vv = *reinterpret_cast<const float4*>(&Vb[(k0 + r) * 64 + c4]);
            Vs[r][c4 + 0] = vv.x; Vs[r][c4 + 1] = vv.y;
            Vs[r][c4 + 2] = vv.z; Vs[r][c4 + 3] = vv.w;
        }
        __syncthreads();

        float s[16];
        #pragma unroll
        for (int j = 0; j < 16; j++) s[j] = 0.f;
        #pragma unroll
        for (int d = 0; d < 64; d++) {
            float qd = Qs[row][d];
            #pragma unroll
            for (int j = 0; j < 16; j++)
                s[j] = fmaf(qd, Ks[d0 + j][d], s[j]);
        }
        #pragma unroll
        for (int j = 0; j < 16; j++) {
            int c = d0 + j;
            s[j] = (k0 + c <= q0 + row) ? s[j] * 0.125f : -1e9f;
        }

        float mloc = s[0];
        #pragma unroll
        for (int j = 1; j < 16; j++) mloc = fmaxf(mloc, s[j]);
        mloc = fmaxf(mloc, __shfl_xor_sync(0xffffffffu, mloc, 1));
        mloc = fmaxf(mloc, __shfl_xor_sync(0xffffffffu, mloc, 2));
        float mnew  = fmaxf(mrow, mloc);
        float alpha = expf(mrow - mnew);

        float psum = 0.f;
        #pragma unroll
        for (int j = 0; j < 16; j++) {
            float p = expf(s[j] - mnew);
            Ps[row][d0 + j] = p;
            psum += p;
        }
        psum += __shfl_xor_sync(0xffffffffu, psum, 1);
        psum += __shfl_xor_sync(0xffffffffu, psum, 2);
        lrow = lrow * alpha + psum;
        mrow = mnew;
        #pragma unroll
        for (int j = 0; j < 16; j++) acc[j] *= alpha;

        __syncthreads();

        #pragma unroll 8
        for (int c2 = 0; c2 < 64; c2++) {
            float p = Ps[row][c2];
            #pragma unroll
            for (int j = 0; j < 16; j++)
                acc[j] = fmaf(p, Vs[c2][d0 + j], acc[j]);
        }
    }

    float inv = 1.f / lrow;
    int b_ = bh >> 4;
    int h_ = bh & 15;
    float* out = ctx + ((size_t)(b_ * Sc + q0 + row)) * Dc + h_ * 64 + d0;
    #pragma unroll
    for (int j = 0; j < 16; j++) out[j] = acc[j] * inv;
}

// ---------------------------------------------------------------------------
// LayerNorm over last dim (D = 1024). One block per row, 256 threads x float4.
// ---------------------------------------------------------------------------
__global__ __launch_bounds__(256)
void ln_kernel(const float* __restrict__ X, const float* __restrict__ gma,
               const float* __restrict__ bta, float* __restrict__ Y)
{
    const int r = blockIdx.x;
    const int t = threadIdx.x;
    float4 v = reinterpret_cast<const float4*>(X + (size_t)r * Dc)[t];
    float s = v.x + v.y + v.z + v.w;
    float q = v.x * v.x + v.y * v.y + v.z * v.z + v.w * v.w;
    #pragma unroll
    for (int o = 16; o; o >>= 1) {
        s += __shfl_xor_sync(0xffffffffu, s, o);
        q += __shfl_xor_sync(0xffffffffu, q, o);
    }
    __shared__ float ss[8], qs[8];
    __shared__ float mu_s, inv_s;
    if ((t & 31) == 0) { ss[t >> 5] = s; qs[t >> 5] = q; }
    __syncthreads();
    if (t == 0) {
        float S = 0.f, Qq = 0.f;
        #pragma unroll
        for (int i = 0; i < 8; i++) { S += ss[i]; Qq += qs[i]; }
        float mu  = S * (1.f / Dc);
        float var = Qq * (1.f / Dc) - mu * mu;
        mu_s  = mu;
        inv_s = rsqrtf(var + EPSc);
    }
    __syncthreads();
    float mu = mu_s, inv = inv_s;
    float4 gv = reinterpret_cast<const float4*>(gma)[t];
    float4 bv = reinterpret_cast<const float4*>(bta)[t];
    float4 o;
    o.x = (v.x - mu) * inv * gv.x + bv.x;
    o.y = (v.y - mu) * inv * gv.y + bv.y;
    o.z = (v.z - mu) * inv * gv.z + bv.z;
    o.w = (v.w - mu) * inv * gv.w + bv.w;
    reinterpret_cast<float4*>(Y + (size_t)r * Dc)[t] = o;
}

// ---------------------------------------------------------------------------
// Launch
// ---------------------------------------------------------------------------
extern "C" void kernel_launch(void* const* d_in, const int* in_sizes, int n_in,
                              void* d_out, int out_size)
{
    const float* query = (const float*)d_in[0];
    const float* key   = (const float*)d_in[1];
    const float* value = (const float*)d_in[2];
    // d_in[3] batch_size, d_in[4] sequence_length, d_in[5] mask (== tril): unused
    const float* Wq = (const float*)d_in[6];
    const float* bq = (const float*)d_in[7];
    const float* Wk = (const float*)d_in[8];
    const float* bk = (const float*)d_in[9];
    const float* Wv = (const float*)d_in[10];
    const float* bv = (const float*)d_in[11];
    const float* Wo = (const float*)d_in[12];
    const float* bo = (const float*)d_in[13];
    const float* ln1_g = (const float*)d_in[14];
    const float* ln1_b = (const float*)d_in[15];
    const float* W1 = (const float*)d_in[16];
    const float* b1 = (const float*)d_in[17];
    const float* W2 = (const float*)d_in[18];
    const float* b2 = (const float*)d_in[19];
    const float* ln2_g = (const float*)d_in[20];
    const float* ln2_b = (const float*)d_in[21];

    float* out   = (float*)d_out;
    float* x2Out = out;
    float* kOut  = out + (size_t)Bc * Hc * Sc * DKc;      // + 4194304
    float* vOut  = kOut + (size_t)Bc * Hc * Sc * DKc;     // + 8388608

    float *pQ, *pCtx, *pY, *pX1, *pH;
    cudaGetSymbolAddress((void**)&pQ,   g_Q);
    cudaGetSymbolAddress((void**)&pCtx, g_ctx);
    cudaGetSymbolAddress((void**)&pY,   g_y);
    cudaGetSymbolAddress((void**)&pX1,  g_x1);
    cudaGetSymbolAddress((void**)&pH,   g_h);

    dim3 blk(256);
    dim3 gridD(Dc / 128, Mr / 128);     // (8, 32)
    dim3 gridF(DFFc / 128, Mr / 128);   // (32, 32)

    // 1. QKV projections (K, V straight into d_out in [B,H,S,DK] layout)
    gemm_mma<false, false, 1><<<gridD, blk>>>(query, Wq, bq, nullptr, pQ,   Dc, Dc);
    gemm_mma<false, false, 1><<<gridD, blk>>>(key,   Wk, bk, nullptr, kOut, Dc, Dc);
    gemm_mma<false, false, 1><<<gridD, blk>>>(value, Wv, bv, nullptr, vOut, Dc, Dc);

    // 2. Causal flash attention -> ctx (concat layout)
    const size_t attn_smem = 4 * 64 * 65 * sizeof(float);   // 66560 B
    cudaFuncSetAttribute(attn_kernel,
                         cudaFuncAttributeMaxDynamicSharedMemorySize,
                         (int)attn_smem);
    dim3 agrid(Sc / 64, Bc * Hc);       // (32, 32)
    attn_kernel<<<agrid, blk, attn_smem>>>(pQ, kOut, vOut, pCtx);

    // 3. Output projection + residual(query) -> y; LN1 -> x1
    gemm_mma<false, true, 0><<<gridD, blk>>>(pCtx, Wo, bo, query, pY, Dc, Dc);
    ln_kernel<<<Mr, blk>>>(pY, ln1_g, ln1_b, pX1);

    // 4. FFN: relu(x1 @ W1 + b1) -> h ; h @ W2 + b2 + x1 -> y ; LN2 -> x2
    gemm_mma<true,  false, 0><<<gridF, blk>>>(pX1, W1, b1, nullptr, pH, DFFc, Dc);
    gemm_mma<false, true,  0><<<gridD, blk>>>(pH,  W2, b2, pX1,     pY, Dc, DFFc);
    ln_kernel<<<Mr, blk>>>(pY, ln2_g, ln2_b, x2Out);
}